// round 2
// baseline (speedup 1.0000x reference)
#include <cuda_runtime.h>

// LSTMModel: 2-layer LSTM (H=50) + FC, B=4096, T=512, input dim 1.
// One block = 32 batches carried through all 512 steps; both layers fused.
// Weights + h-state in SMEM, c-state in registers.

#define HID   50
#define G4    200      // 4*H
#define TLEN  512
#define BT    32       // batches per block
#define NT    416      // threads per block (13 warps), 400 active
#define ACTV  400
#define WST   51       // weight row stride (conflict-free: gcd(51,32)=1 -> 19 step)
#define HST   33       // h row stride (stride-33 -> conflict-free writes)
#define XCH   64       // x chunk (timesteps staged in smem)

__device__ __forceinline__ float fsig(float v) {
    return __fdividef(1.0f, 1.0f + __expf(-v));
}
__device__ __forceinline__ float ftanh(float v) {
    return __fdividef(2.0f, 1.0f + __expf(-2.0f * v)) - 1.0f;
}

extern __shared__ float smem[];

__global__ __launch_bounds__(NT, 1) void lstm2_kernel(
    const float* __restrict__ x,
    const float* __restrict__ w_ih0, const float* __restrict__ w_hh0,
    const float* __restrict__ b_ih0, const float* __restrict__ b_hh0,
    const float* __restrict__ w_ih1, const float* __restrict__ w_hh1,
    const float* __restrict__ b_ih1, const float* __restrict__ b_hh1,
    const float* __restrict__ fc_w,  const float* __restrict__ fc_b,
    float* __restrict__ out)
{
    float* whh0  = smem;                 // [G4][WST]
    float* wih1  = whh0 + G4 * WST;      // [G4][WST]
    float* whh1  = wih1 + G4 * WST;      // [G4][WST]
    float* wih0v = whh1 + G4 * WST;      // [G4]
    float* bias0 = wih0v + G4;           // [G4]  (b_ih0 + b_hh0)
    float* bias1 = bias0 + G4;           // [G4]  (b_ih1 + b_hh1)
    float* fcw   = bias1 + G4;           // [64]
    float* h1s   = fcw + 64;             // [HID][HST]
    float* h2s   = h1s + HID * HST;      // [HID][HST]
    float* xs    = h2s + HID * HST;      // [XCH][HST]

    const int tid   = threadIdx.x;
    const int bbase = blockIdx.x * BT;

    // ---- stage weights into shared ----
    for (int idx = tid; idx < G4 * HID; idx += NT) {
        int g = idx / HID, k = idx - g * HID;
        whh0[g * WST + k] = w_hh0[idx];
        wih1[g * WST + k] = w_ih1[idx];
        whh1[g * WST + k] = w_hh1[idx];
    }
    for (int g = tid; g < G4; g += NT) {
        wih0v[g] = w_ih0[g];
        bias0[g] = b_ih0[g] + b_hh0[g];
        bias1[g] = b_ih1[g] + b_hh1[g];
    }
    for (int k = tid; k < HID; k += NT) fcw[k] = fc_w[k];
    for (int i = tid; i < HID * HST; i += NT) { h1s[i] = 0.0f; h2s[i] = 0.0f; }
    __syncthreads();

    // ---- per-thread static assignment: (j = hidden unit, bg = batch group) ----
    const bool active = (tid < ACTV);
    int j = 0, bg = 0;
    int rb[4];            // weight row offsets for gates i,f,g,o of unit j
    int bl[4];            // the 4 local batch indices this thread owns
    float wx[4], bb0[4], bb1[4];
    float c1[4] = {0.f, 0.f, 0.f, 0.f};
    float c2[4] = {0.f, 0.f, 0.f, 0.f};
    if (active) {
        bg = tid / HID;
        j  = tid - bg * HID;
        #pragma unroll
        for (int q = 0; q < 4; q++) {
            int g = q * HID + j;
            rb[q]  = g * WST;
            wx[q]  = wih0v[g];
            bb0[q] = bias0[g];
            bb1[q] = bias1[g];
        }
        #pragma unroll
        for (int r = 0; r < 4; r++) bl[r] = bg + 8 * r;
    }

    float h1n[4], h2n[4];

    for (int t = 0; t < TLEN; t++) {
        // stage x chunk (coalesced gmem, conflict-free smem)
        if ((t & (XCH - 1)) == 0) {
            for (int idx = tid; idx < BT * XCH; idx += NT) {
                int bb = idx >> 6, tt = idx & (XCH - 1);
                xs[tt * HST + bb] = x[(bbase + bb) * TLEN + t + tt];
            }
            __syncthreads();
        }

        // ============ layer 1 ============
        float acc[4][4];
        if (active) {
            const int tx = (t & (XCH - 1)) * HST;
            #pragma unroll
            for (int r = 0; r < 4; r++) {
                float xv = xs[tx + bl[r]];
                #pragma unroll
                for (int q = 0; q < 4; q++) acc[q][r] = bb0[q] + xv * wx[q];
            }
            #pragma unroll 10
            for (int k = 0; k < HID; k++) {
                float w0 = whh0[rb[0] + k], w1 = whh0[rb[1] + k];
                float w2 = whh0[rb[2] + k], w3 = whh0[rb[3] + k];
                #pragma unroll
                for (int r = 0; r < 4; r++) {
                    float hv = h1s[k * HST + bl[r]];
                    acc[0][r] += w0 * hv; acc[1][r] += w1 * hv;
                    acc[2][r] += w2 * hv; acc[3][r] += w3 * hv;
                }
            }
            #pragma unroll
            for (int r = 0; r < 4; r++) {
                float iv = fsig(acc[0][r]);
                float fv = fsig(acc[1][r]);
                float gv = ftanh(acc[2][r]);
                float ov = fsig(acc[3][r]);
                c1[r]  = fv * c1[r] + iv * gv;
                h1n[r] = ov * ftanh(c1[r]);
            }
        }
        __syncthreads();
        if (active) {
            #pragma unroll
            for (int r = 0; r < 4; r++) h1s[j * HST + bl[r]] = h1n[r];
        }
        __syncthreads();

        // ============ layer 2 ============
        if (active) {
            #pragma unroll
            for (int q = 0; q < 4; q++) {
                #pragma unroll
                for (int r = 0; r < 4; r++) acc[q][r] = bb1[q];
            }
            #pragma unroll 10
            for (int k = 0; k < HID; k++) {   // input path: w_ih1 @ h1
                float w0 = wih1[rb[0] + k], w1 = wih1[rb[1] + k];
                float w2 = wih1[rb[2] + k], w3 = wih1[rb[3] + k];
                #pragma unroll
                for (int r = 0; r < 4; r++) {
                    float hv = h1s[k * HST + bl[r]];
                    acc[0][r] += w0 * hv; acc[1][r] += w1 * hv;
                    acc[2][r] += w2 * hv; acc[3][r] += w3 * hv;
                }
            }
            #pragma unroll 10
            for (int k = 0; k < HID; k++) {   // recurrent path: w_hh1 @ h2
                float w0 = whh1[rb[0] + k], w1 = whh1[rb[1] + k];
                float w2 = whh1[rb[2] + k], w3 = whh1[rb[3] + k];
                #pragma unroll
                for (int r = 0; r < 4; r++) {
                    float hv = h2s[k * HST + bl[r]];
                    acc[0][r] += w0 * hv; acc[1][r] += w1 * hv;
                    acc[2][r] += w2 * hv; acc[3][r] += w3 * hv;
                }
            }
            #pragma unroll
            for (int r = 0; r < 4; r++) {
                float iv = fsig(acc[0][r]);
                float fv = fsig(acc[1][r]);
                float gv = ftanh(acc[2][r]);
                float ov = fsig(acc[3][r]);
                c2[r]  = fv * c2[r] + iv * gv;
                h2n[r] = ov * ftanh(c2[r]);
            }
        }
        __syncthreads();
        if (active) {
            #pragma unroll
            for (int r = 0; r < 4; r++) h2s[j * HST + bl[r]] = h2n[r];
        }
        __syncthreads();
    }

    // ---- final FC on last h2 ----
    if (tid < BT) {
        float s = fc_b[0];
        #pragma unroll 10
        for (int k = 0; k < HID; k++) s += h2s[k * HST + tid] * fcw[k];
        out[bbase + tid] = s;
    }
}

extern "C" void kernel_launch(void* const* d_in, const int* in_sizes, int n_in,
                              void* d_out, int out_size) {
    const float* x     = (const float*)d_in[0];
    const float* w_ih0 = (const float*)d_in[1];
    const float* w_hh0 = (const float*)d_in[2];
    const float* b_ih0 = (const float*)d_in[3];
    const float* b_hh0 = (const float*)d_in[4];
    const float* w_ih1 = (const float*)d_in[5];
    const float* w_hh1 = (const float*)d_in[6];
    const float* b_ih1 = (const float*)d_in[7];
    const float* b_hh1 = (const float*)d_in[8];
    const float* fc_w  = (const float*)d_in[9];
    const float* fc_b  = (const float*)d_in[10];
    float* out = (float*)d_out;

    const size_t smem_bytes =
        (size_t)(3 * G4 * WST + 3 * G4 + 64 + 2 * HID * HST + XCH * HST) * sizeof(float);

    cudaFuncSetAttribute(lstm2_kernel,
                         cudaFuncAttributeMaxDynamicSharedMemorySize,
                         (int)smem_bytes);

    const int nblocks = 4096 / BT;  // 128
    lstm2_kernel<<<nblocks, NT, smem_bytes>>>(
        x, w_ih0, w_hh0, b_ih0, b_hh0,
        w_ih1, w_hh1, b_ih1, b_hh1, fc_w, fc_b, out);
}

// round 3
// speedup vs baseline: 1.5431x; 1.5431x over previous
#include <cuda_runtime.h>
#include <cstdint>

// 2-layer LSTM (H=50) + FC. B=4096, T=512, in-dim 1.
// Gate-packed f32x2 math: acc_if = (i,f), acc_go = (g,o) per batch.
// Weights interleaved per (j,k) as float4 (i,f,g,o) -> ld.shared.v2.u64.
// Warp mapping: bg = tid&7 (batch group), j = tid>>3 (hidden unit) so
// weight loads broadcast (4 addr/warp) and h loads are 1 wavefront.

typedef unsigned long long u64;

#define HID   50
#define BT    32
#define NT    400
#define TLEN  512

// byte offsets into dynamic smem
#define OFF_WP0 0          // packed w_hh0  [50][50] float4 = 40000
#define OFF_WPA 40000      // packed w_ih1
#define OFF_WPB 80000      // packed w_hh1
#define OFF_H1  120000     // h1 double buffer: 2 x (50*32*4 = 6400)
#define OFF_H2  132800     // h2 double buffer
#define OFF_XS  145600     // x chunk: 64 steps x 32 batches x 4 = 8192
#define OFF_B0  153792     // packed bias l1: float4[50]
#define OFF_B1  154592     // packed bias l2
#define OFF_WX  155392     // packed w_ih0: float4[50]
#define OFF_FCW 156192     // fc weights: 50 floats
#define SMEM_BYTES 156416

#define HBUF 6400          // bytes per h buffer

__device__ __forceinline__ u64 pk2(float lo, float hi) {
    u64 r; asm("mov.b64 %0, {%1, %2};" : "=l"(r) : "f"(lo), "f"(hi)); return r;
}
__device__ __forceinline__ void upk2(u64 v, float& lo, float& hi) {
    asm("mov.b64 {%0, %1}, %2;" : "=f"(lo), "=f"(hi) : "l"(v));
}
__device__ __forceinline__ void ffma2(u64& d, u64 a, u64 b) {
    asm("fma.rn.f32x2 %0, %1, %2, %0;" : "+l"(d) : "l"(a), "l"(b));
}
__device__ __forceinline__ float fsig(float v) {
    return __fdividef(1.0f, 1.0f + __expf(-v));
}
__device__ __forceinline__ float ftanh(float v) {
    return __fdividef(2.0f, 1.0f + __expf(-2.0f * v)) - 1.0f;
}

// 50-step gate-packed GEMV: acc += W[j] * h  (4 batches, 2 gate-pairs)
__device__ __forceinline__ void gemm50(uint32_t wa, uint32_t ha,
                                       u64 aif[4], u64 ago[4]) {
#pragma unroll
    for (int k = 0; k < HID; ++k) {
        u64 wif, wgo;
        asm volatile("ld.shared.v2.u64 {%0, %1}, [%2];"
                     : "=l"(wif), "=l"(wgo) : "r"(wa + 16u * k));
        float h0, h1, h2, h3;
        asm volatile("ld.shared.v4.f32 {%0, %1, %2, %3}, [%4];"
                     : "=f"(h0), "=f"(h1), "=f"(h2), "=f"(h3)
                     : "r"(ha + 128u * k));
        u64 hh;
        hh = pk2(h0, h0); ffma2(aif[0], wif, hh); ffma2(ago[0], wgo, hh);
        hh = pk2(h1, h1); ffma2(aif[1], wif, hh); ffma2(ago[1], wgo, hh);
        hh = pk2(h2, h2); ffma2(aif[2], wif, hh); ffma2(ago[2], wgo, hh);
        hh = pk2(h3, h3); ffma2(aif[3], wif, hh); ffma2(ago[3], wgo, hh);
    }
}

__device__ __forceinline__ void act_update(const u64 aif[4], const u64 ago[4],
                                           float c[4], float hv[4]) {
#pragma unroll
    for (int r = 0; r < 4; ++r) {
        float pi, pf, pg, po;
        upk2(aif[r], pi, pf);
        upk2(ago[r], pg, po);
        float iv = fsig(pi);
        float fv = fsig(pf);
        float gv = ftanh(pg);
        float ov = fsig(po);
        c[r]  = fv * c[r] + iv * gv;
        hv[r] = ov * ftanh(c[r]);
    }
}

extern __shared__ float smem[];

__global__ __launch_bounds__(NT, 1) void lstm2_kernel(
    const float* __restrict__ x,
    const float* __restrict__ w_ih0, const float* __restrict__ w_hh0,
    const float* __restrict__ b_ih0, const float* __restrict__ b_hh0,
    const float* __restrict__ w_ih1, const float* __restrict__ w_hh1,
    const float* __restrict__ b_ih1, const float* __restrict__ b_hh1,
    const float* __restrict__ fc_w,  const float* __restrict__ fc_b,
    float* __restrict__ out)
{
    char* sb = (char*)smem;
    const uint32_t sa = (uint32_t)__cvta_generic_to_shared(smem);
    const int tid   = threadIdx.x;
    const int bbase = blockIdx.x * BT;

    // ---- stage packed weights: wp[j][k] = (Wi[j][k], Wf, Wg, Wo) ----
    {
        float4* wp0 = (float4*)(sb + OFF_WP0);
        float4* wpA = (float4*)(sb + OFF_WPA);
        float4* wpB = (float4*)(sb + OFF_WPB);
        for (int idx = tid; idx < HID * HID; idx += NT) {
            int jj = idx / HID, kk = idx - jj * HID;
            int r0 = jj * HID + kk;
            wp0[idx] = make_float4(w_hh0[r0], w_hh0[r0 + 50 * HID],
                                   w_hh0[r0 + 100 * HID], w_hh0[r0 + 150 * HID]);
            wpA[idx] = make_float4(w_ih1[r0], w_ih1[r0 + 50 * HID],
                                   w_ih1[r0 + 100 * HID], w_ih1[r0 + 150 * HID]);
            wpB[idx] = make_float4(w_hh1[r0], w_hh1[r0 + 50 * HID],
                                   w_hh1[r0 + 100 * HID], w_hh1[r0 + 150 * HID]);
        }
        float4* b0p = (float4*)(sb + OFF_B0);
        float4* b1p = (float4*)(sb + OFF_B1);
        float4* wxp = (float4*)(sb + OFF_WX);
        float*  fcs = (float*)(sb + OFF_FCW);
        for (int g = tid; g < HID; g += NT) {
            b0p[g] = make_float4(b_ih0[g]       + b_hh0[g],
                                 b_ih0[g + 50]  + b_hh0[g + 50],
                                 b_ih0[g + 100] + b_hh0[g + 100],
                                 b_ih0[g + 150] + b_hh0[g + 150]);
            b1p[g] = make_float4(b_ih1[g]       + b_hh1[g],
                                 b_ih1[g + 50]  + b_hh1[g + 50],
                                 b_ih1[g + 100] + b_hh1[g + 100],
                                 b_ih1[g + 150] + b_hh1[g + 150]);
            wxp[g] = make_float4(w_ih0[g], w_ih0[g + 50],
                                 w_ih0[g + 100], w_ih0[g + 150]);
            fcs[g] = fc_w[g];
        }
        // zero both h double-buffers (h1 + h2 = 25600 B = 6400 floats)
        float* hz = (float*)(sb + OFF_H1);
        for (int idx = tid; idx < 6400; idx += NT) hz[idx] = 0.0f;
    }
    __syncthreads();

    // ---- per-thread mapping ----
    const int bg = tid & 7;     // batch group: batches 4*bg .. 4*bg+3
    const int j  = tid >> 3;    // hidden unit (0..49)

    u64 b0if, b0go, b1if, b1go, wxif, wxgo;
    {
        float4 t4 = ((float4*)(sb + OFF_B0))[j];
        b0if = pk2(t4.x, t4.y); b0go = pk2(t4.z, t4.w);
        t4 = ((float4*)(sb + OFF_B1))[j];
        b1if = pk2(t4.x, t4.y); b1go = pk2(t4.z, t4.w);
        t4 = ((float4*)(sb + OFF_WX))[j];
        wxif = pk2(t4.x, t4.y); wxgo = pk2(t4.z, t4.w);
    }

    const uint32_t wa0 = sa + OFF_WP0 + (uint32_t)j * 800u;
    const uint32_t waA = sa + OFF_WPA + (uint32_t)j * 800u;
    const uint32_t waB = sa + OFF_WPB + (uint32_t)j * 800u;
    const uint32_t h1rd = sa + OFF_H1 + (uint32_t)bg * 16u;
    const uint32_t h2rd = sa + OFF_H2 + (uint32_t)bg * 16u;
    const uint32_t xrd  = sa + OFF_XS + (uint32_t)bg * 16u;

    float c1[4] = {0.f, 0.f, 0.f, 0.f};
    float c2[4] = {0.f, 0.f, 0.f, 0.f};
    float h1v[4], h2v[4];

    for (int t = 0; t < TLEN; ++t) {
        // stage 64-step x chunk (coalesced)
        if ((t & 63) == 0) {
            float* xs = (float*)(sb + OFF_XS);
            for (int idx = tid; idx < BT * 64; idx += NT) {
                int b = idx >> 6, tt = idx & 63;
                xs[tt * BT + b] = x[(bbase + b) * TLEN + t + tt];
            }
            __syncthreads();
        }

        const uint32_t cur = (uint32_t)(t & 1) * HBUF;
        const uint32_t nxt = HBUF - cur;

        // ============ layer 1 ============
        u64 aif[4], ago[4];
        {
            float x0, x1, x2, x3;
            asm volatile("ld.shared.v4.f32 {%0, %1, %2, %3}, [%4];"
                         : "=f"(x0), "=f"(x1), "=f"(x2), "=f"(x3)
                         : "r"(xrd + (uint32_t)(t & 63) * 128u));
            u64 hh;
            hh = pk2(x0, x0); aif[0] = b0if; ffma2(aif[0], wxif, hh);
                              ago[0] = b0go; ffma2(ago[0], wxgo, hh);
            hh = pk2(x1, x1); aif[1] = b0if; ffma2(aif[1], wxif, hh);
                              ago[1] = b0go; ffma2(ago[1], wxgo, hh);
            hh = pk2(x2, x2); aif[2] = b0if; ffma2(aif[2], wxif, hh);
                              ago[2] = b0go; ffma2(ago[2], wxgo, hh);
            hh = pk2(x3, x3); aif[3] = b0if; ffma2(aif[3], wxif, hh);
                              ago[3] = b0go; ffma2(ago[3], wxgo, hh);
        }
        gemm50(wa0, h1rd + cur, aif, ago);
        act_update(aif, ago, c1, h1v);
        *(float4*)(sb + OFF_H1 + nxt + j * 128 + bg * 16) =
            make_float4(h1v[0], h1v[1], h1v[2], h1v[3]);
        __syncthreads();

        // ============ layer 2 ============
        aif[0] = b1if; aif[1] = b1if; aif[2] = b1if; aif[3] = b1if;
        ago[0] = b1go; ago[1] = b1go; ago[2] = b1go; ago[3] = b1go;
        gemm50(waA, h1rd + nxt, aif, ago);   // input path: new h1
        gemm50(waB, h2rd + cur, aif, ago);   // recurrent path: old h2
        act_update(aif, ago, c2, h2v);
        *(float4*)(sb + OFF_H2 + nxt + j * 128 + bg * 16) =
            make_float4(h2v[0], h2v[1], h2v[2], h2v[3]);
        __syncthreads();
    }

    // ---- final FC (last h2 lives in buffer 0 after t=511) ----
    if (tid < BT) {
        const float* h2f = (const float*)(sb + OFF_H2);
        const float* fcs = (const float*)(sb + OFF_FCW);
        float s = fc_b[0];
#pragma unroll 10
        for (int k = 0; k < HID; ++k) s += h2f[k * BT + tid] * fcs[k];
        out[bbase + tid] = s;
    }
}

extern "C" void kernel_launch(void* const* d_in, const int* in_sizes, int n_in,
                              void* d_out, int out_size) {
    const float* x     = (const float*)d_in[0];
    const float* w_ih0 = (const float*)d_in[1];
    const float* w_hh0 = (const float*)d_in[2];
    const float* b_ih0 = (const float*)d_in[3];
    const float* b_hh0 = (const float*)d_in[4];
    const float* w_ih1 = (const float*)d_in[5];
    const float* w_hh1 = (const float*)d_in[6];
    const float* b_ih1 = (const float*)d_in[7];
    const float* b_hh1 = (const float*)d_in[8];
    const float* fc_w  = (const float*)d_in[9];
    const float* fc_b  = (const float*)d_in[10];
    float* out = (float*)d_out;

    cudaFuncSetAttribute(lstm2_kernel,
                         cudaFuncAttributeMaxDynamicSharedMemorySize,
                         SMEM_BYTES);

    lstm2_kernel<<<4096 / BT, NT, SMEM_BYTES>>>(
        x, w_ih0, w_hh0, b_ih0, b_hh0,
        w_ih1, w_hh1, b_ih1, b_hh1, fc_w, fc_b, out);
}